// round 6
// baseline (speedup 1.0000x reference)
#include <cuda_runtime.h>
#include <math.h>

#define NMAX 50000
#define EMAX 800000

// Scratch (allocation-free rule: __device__ globals)
__device__ float g_h[NMAX * 128];     // x @ W1
__device__ float g_agg[NMAX * 128];   // layer-1 aggregation, then relu'd hidden
__device__ float g_h2[NMAX * 16];     // hidden @ W2
__device__ float g_agg2[NMAX * 16];   // layer-2 aggregation
__device__ float g_dinv[NMAX];
__device__ int   g_deg[NMAX];
__device__ int   g_row[EMAX];
__device__ int   g_col[EMAX];
__device__ int   g_is32;              // 1 if edge_index arrived as int32

// ---------------------------------------------------------------------------
// Detect whether edge data is int32 or int64.
// Genuine int64 indices (< 50000) have zero high 32 bits in every word.
// int32-packed data has a random second index in the high word.
// ---------------------------------------------------------------------------
__global__ void k_detect(const unsigned long long* __restrict__ ei, int nwords) {
    if (threadIdx.x == 0 && blockIdx.x == 0) {
        int n = nwords < 64 ? nwords : 64;
        unsigned long long acc = 0;
        for (int i = 0; i < n; i++) acc |= (ei[i] >> 32);
        g_is32 = (acc != 0ULL) ? 1 : 0;
    }
}

// ---------------------------------------------------------------------------
// Convert edges to int32 row/col arrays under either interpretation.
// ---------------------------------------------------------------------------
__global__ void k_convert(const void* __restrict__ ei, int E) {
    int e = blockIdx.x * blockDim.x + threadIdx.x;
    if (e >= E) return;
    int r, c;
    if (g_is32) {
        const int* p = (const int*)ei;
        r = p[e];
        c = p[E + e];
    } else {
        const long long* p = (const long long*)ei;
        r = (int)p[e];
        c = (int)p[E + e];
    }
    g_row[e] = r;
    g_col[e] = c;
}

// ---------------------------------------------------------------------------
// init: zero aggregation buffers, deg = 1 (self loop)
// ---------------------------------------------------------------------------
__global__ void k_init(int N) {
    int i = blockIdx.x * blockDim.x + threadIdx.x;
    if (i < N * 128) g_agg[i] = 0.0f;
    if (i < N * 16)  g_agg2[i] = 0.0f;
    if (i < N)       g_deg[i] = 1;
}

// ---------------------------------------------------------------------------
// degree count over edge destinations
// ---------------------------------------------------------------------------
__global__ void k_count(int E, int N) {
    int e = blockIdx.x * blockDim.x + threadIdx.x;
    if (e < E) {
        int c = g_col[e];
        if ((unsigned)c < (unsigned)N) atomicAdd(&g_deg[c], 1);
    }
}

__global__ void k_dinv(int N) {
    int v = blockIdx.x * blockDim.x + threadIdx.x;
    if (v < N) g_dinv[v] = rsqrtf((float)g_deg[v]);
}

// ---------------------------------------------------------------------------
// GEMM1: g_h[N,128] = x[N,128] @ W1[128,128]
// block tile 64 rows x 128 cols, 256 threads, thread tile 4x8, BK=32
// ---------------------------------------------------------------------------
__global__ void k_gemm1(const float* __restrict__ X, const float* __restrict__ W, int N) {
    __shared__ float Xs[64][33];
    __shared__ float Ws[32][128];

    int t  = threadIdx.x;
    int tx = t & 15;   // col group: cols tx*8 .. tx*8+7
    int ty = t >> 4;   // row group: rows ty*4 .. ty*4+3
    int row0 = blockIdx.x * 64;

    float acc[4][8];
#pragma unroll
    for (int i = 0; i < 4; i++)
#pragma unroll
        for (int j = 0; j < 8; j++) acc[i][j] = 0.0f;

    for (int kk = 0; kk < 128; kk += 32) {
        for (int i = t; i < 64 * 32; i += 256) {
            int r = i >> 5, k = i & 31;
            int gr = row0 + r;
            Xs[r][k] = (gr < N) ? X[gr * 128 + kk + k] : 0.0f;
        }
        for (int i = t; i < 32 * 128; i += 256) {
            int k = i >> 7, c = i & 127;
            Ws[k][c] = W[(kk + k) * 128 + c];
        }
        __syncthreads();

#pragma unroll
        for (int k = 0; k < 32; k++) {
            float a[4], b[8];
#pragma unroll
            for (int i = 0; i < 4; i++) a[i] = Xs[ty * 4 + i][k];
#pragma unroll
            for (int j = 0; j < 8; j++) b[j] = Ws[k][tx * 8 + j];
#pragma unroll
            for (int i = 0; i < 4; i++)
#pragma unroll
                for (int j = 0; j < 8; j++) acc[i][j] += a[i] * b[j];
        }
        __syncthreads();
    }

#pragma unroll
    for (int i = 0; i < 4; i++) {
        int gr = row0 + ty * 4 + i;
        if (gr < N) {
            float4* dst = (float4*)&g_h[gr * 128 + tx * 8];
            dst[0] = make_float4(acc[i][0], acc[i][1], acc[i][2], acc[i][3]);
            dst[1] = make_float4(acc[i][4], acc[i][5], acc[i][6], acc[i][7]);
        }
    }
}

// ---------------------------------------------------------------------------
// Scatter layer 1: warp per edge. agg[col] += norm * h[row]  (128 floats)
// ---------------------------------------------------------------------------
__global__ void k_scatter1(int E, int N) {
    int warp = (blockIdx.x * blockDim.x + threadIdx.x) >> 5;
    int lane = threadIdx.x & 31;
    if (warp >= E) return;
    int r = g_row[warp];
    int c = g_col[warp];
    if ((unsigned)r >= (unsigned)N || (unsigned)c >= (unsigned)N) return;
    float nrm = g_dinv[r] * g_dinv[c];
    float4 v = ((const float4*)g_h)[r * 32 + lane];
    float* dst = &g_agg[c * 128 + lane * 4];
    atomicAdd(dst + 0, v.x * nrm);
    atomicAdd(dst + 1, v.y * nrm);
    atomicAdd(dst + 2, v.z * nrm);
    atomicAdd(dst + 3, v.w * nrm);
}

// ---------------------------------------------------------------------------
// Self-loop + bias + ReLU (in place into g_agg): agg = relu(agg + dinv^2*h + b1)
// ---------------------------------------------------------------------------
__global__ void k_post1(const float* __restrict__ b1, int N) {
    int i = blockIdx.x * blockDim.x + threadIdx.x;   // float4 index
    if (i >= N * 32) return;
    int v = i >> 5, l = i & 31;
    float d = g_dinv[v];
    float di2 = d * d;
    float4 a = ((const float4*)g_agg)[i];
    float4 h = ((const float4*)g_h)[i];
    float4 b = ((const float4*)b1)[l];
    float4 o;
    o.x = fmaxf(a.x + di2 * h.x + b.x, 0.0f);
    o.y = fmaxf(a.y + di2 * h.y + b.y, 0.0f);
    o.z = fmaxf(a.z + di2 * h.z + b.z, 0.0f);
    o.w = fmaxf(a.w + di2 * h.w + b.w, 0.0f);
    ((float4*)g_agg)[i] = o;
}

// ---------------------------------------------------------------------------
// GEMM2: g_h2[N,16] = g_agg[N,128] @ W2[128,16]
// ---------------------------------------------------------------------------
__global__ void k_gemm2(const float* __restrict__ W2, int N) {
    __shared__ float Ws[128 * 16];
    __shared__ float Xs[64][129];

    int t  = threadIdx.x;
    int tx = t & 15;
    int ty = t >> 4;
    int row0 = blockIdx.x * 64;

    for (int i = t; i < 128 * 16; i += 256) Ws[i] = W2[i];
    for (int i = t; i < 64 * 128; i += 256) {
        int r = i >> 7, k = i & 127;
        int gr = row0 + r;
        Xs[r][k] = (gr < N) ? g_agg[gr * 128 + k] : 0.0f;
    }
    __syncthreads();

    float acc[4] = {0.0f, 0.0f, 0.0f, 0.0f};
#pragma unroll
    for (int k = 0; k < 128; k++) {
        float w = Ws[k * 16 + tx];
#pragma unroll
        for (int i = 0; i < 4; i++) acc[i] += Xs[ty * 4 + i][k] * w;
    }
#pragma unroll
    for (int i = 0; i < 4; i++) {
        int gr = row0 + ty * 4 + i;
        if (gr < N) g_h2[gr * 16 + tx] = acc[i];
    }
}

// ---------------------------------------------------------------------------
// Scatter layer 2: 16 threads per edge. agg2[col][c] += norm * h2[row][c]
// ---------------------------------------------------------------------------
__global__ void k_scatter2(int E, int N) {
    long long tid = (long long)blockIdx.x * blockDim.x + threadIdx.x;
    if (tid >= (long long)E * 16) return;
    int e = (int)(tid >> 4);
    int c = (int)(tid & 15);
    int r  = g_row[e];
    int cl = g_col[e];
    if ((unsigned)r >= (unsigned)N || (unsigned)cl >= (unsigned)N) return;
    float nrm = g_dinv[r] * g_dinv[cl];
    atomicAdd(&g_agg2[cl * 16 + c], g_h2[r * 16 + c] * nrm);
}

// ---------------------------------------------------------------------------
// Final: self-loop + bias + log_softmax over 16 classes -> out
// ---------------------------------------------------------------------------
__global__ void k_final(const float* __restrict__ b2, float* __restrict__ out, int N) {
    int v = blockIdx.x * blockDim.x + threadIdx.x;
    if (v >= N) return;
    float d = g_dinv[v];
    float di2 = d * d;
    float vals[16];
    float m = -1e30f;
#pragma unroll
    for (int q = 0; q < 4; q++) {
        float4 a = ((const float4*)g_agg2)[v * 4 + q];
        float4 h = ((const float4*)g_h2)[v * 4 + q];
        float4 b = ((const float4*)b2)[q];
        vals[q * 4 + 0] = a.x + di2 * h.x + b.x;
        vals[q * 4 + 1] = a.y + di2 * h.y + b.y;
        vals[q * 4 + 2] = a.z + di2 * h.z + b.z;
        vals[q * 4 + 3] = a.w + di2 * h.w + b.w;
    }
#pragma unroll
    for (int c = 0; c < 16; c++) m = fmaxf(m, vals[c]);
    float s = 0.0f;
#pragma unroll
    for (int c = 0; c < 16; c++) s += expf(vals[c] - m);
    float lse = m + logf(s);
#pragma unroll
    for (int c = 0; c < 16; c++) out[v * 16 + c] = vals[c] - lse;
}

// ---------------------------------------------------------------------------
extern "C" void kernel_launch(void* const* d_in, const int* in_sizes, int n_in,
                              void* d_out, int out_size) {
    const float* x  = (const float*)d_in[0];
    const void*  ei = (const void*)d_in[1];
    const float* W1 = (const float*)d_in[2];
    const float* b1 = (const float*)d_in[3];
    const float* W2 = (const float*)d_in[4];
    const float* b2 = (const float*)d_in[5];
    float* out = (float*)d_out;

    int N = in_sizes[0] / 128;
    int E = in_sizes[1] / 2;

    // dtype sniff + edge conversion to int32
    k_detect<<<1, 32>>>((const unsigned long long*)ei, E);
    k_convert<<<(E + 255) / 256, 256>>>(ei, E);

    // init + degrees + norm
    k_init<<<(N * 128 + 255) / 256, 256>>>(N);
    k_count<<<(E + 255) / 256, 256>>>(E, N);
    k_dinv<<<(N + 255) / 256, 256>>>(N);

    // layer 1
    k_gemm1<<<(N + 63) / 64, 256>>>(x, W1, N);
    {
        long long threads = (long long)E * 32;
        k_scatter1<<<(unsigned)((threads + 255) / 256), 256>>>(E, N);
    }
    k_post1<<<(N * 32 + 255) / 256, 256>>>(b1, N);

    // layer 2
    k_gemm2<<<(N + 63) / 64, 256>>>(W2, N);
    {
        long long threads = (long long)E * 16;
        k_scatter2<<<(unsigned)((threads + 255) / 256), 256>>>(E, N);
    }
    k_final<<<(N + 255) / 256, 256>>>(b2, out, N);
}

// round 8
// speedup vs baseline: 1.9827x; 1.9827x over previous
#include <cuda_runtime.h>
#include <math.h>

#define NMAX 50000
#define EMAX 800000

// Scratch (allocation-free rule: __device__ globals)
__device__ float g_h[NMAX * 128];     // x @ W1
__device__ float g_agg[NMAX * 128];   // relu'd hidden after layer-1 aggregation
__device__ float g_h2[NMAX * 16];     // hidden @ W2
__device__ float g_dinv[NMAX];
__device__ int   g_indeg[NMAX];       // in-degree (without self loop)
__device__ int   g_row[EMAX];
__device__ int   g_col[EMAX];
__device__ int   g_off[NMAX + 1];     // CSR offsets by destination
__device__ int   g_chunk[256];        // scan partials
__device__ int   g_cursor[NMAX];      // fill cursors
__device__ int2  g_edge[EMAX];        // CSR payload: (src, __float_as_int(norm))
__device__ int   g_is32;              // 1 if edge_index arrived as int32

// ---------------------------------------------------------------------------
// dtype sniff: int64 indices < 50000 have zero high words; int32-packed don't.
// ---------------------------------------------------------------------------
__global__ void k_detect(const unsigned long long* __restrict__ ei, int nwords) {
    if (threadIdx.x == 0 && blockIdx.x == 0) {
        int n = nwords < 64 ? nwords : 64;
        unsigned long long acc = 0;
        for (int i = 0; i < n; i++) acc |= (ei[i] >> 32);
        g_is32 = (acc != 0ULL) ? 1 : 0;
    }
}

__global__ void k_zero(int N) {
    int i = blockIdx.x * blockDim.x + threadIdx.x;
    if (i < N) g_indeg[i] = 0;
}

// ---------------------------------------------------------------------------
// Convert edges to int32 row/col arrays AND count in-degrees.
// ---------------------------------------------------------------------------
__global__ void k_convert(const void* __restrict__ ei, int E, int N) {
    int e = blockIdx.x * blockDim.x + threadIdx.x;
    if (e >= E) return;
    int r, c;
    if (g_is32) {
        const int* p = (const int*)ei;
        r = p[e];
        c = p[E + e];
    } else {
        const long long* p = (const long long*)ei;
        r = (int)p[e];
        c = (int)p[E + e];
    }
    g_row[e] = r;
    g_col[e] = c;
    if ((unsigned)c < (unsigned)N) atomicAdd(&g_indeg[c], 1);
}

__global__ void k_dinv(int N) {
    int v = blockIdx.x * blockDim.x + threadIdx.x;
    if (v < N) g_dinv[v] = rsqrtf((float)(g_indeg[v] + 1));  // +1 self loop
}

// ---------------------------------------------------------------------------
// Two-level exclusive scan of indeg -> g_off
// ---------------------------------------------------------------------------
__global__ void k_scan1(int N) {
    __shared__ int s[256];
    int t = threadIdx.x;
    int i = blockIdx.x * 256 + t;
    int v = (i < N) ? g_indeg[i] : 0;
    s[t] = v;
    __syncthreads();
#pragma unroll
    for (int o = 1; o < 256; o <<= 1) {
        int u = (t >= o) ? s[t - o] : 0;
        __syncthreads();
        s[t] += u;
        __syncthreads();
    }
    if (i < N) g_off[i] = s[t] - v;          // exclusive within chunk
    if (t == 255) g_chunk[blockIdx.x] = s[255];
}

__global__ void k_scan2(int nchunks) {
    __shared__ int s[256];
    int t = threadIdx.x;
    int v = (t < nchunks) ? g_chunk[t] : 0;
    s[t] = v;
    __syncthreads();
#pragma unroll
    for (int o = 1; o < 256; o <<= 1) {
        int u = (t >= o) ? s[t - o] : 0;
        __syncthreads();
        s[t] += u;
        __syncthreads();
    }
    g_chunk[t] = s[t] - v;                   // exclusive chunk bases
}

__global__ void k_scan3(int N, int E) {
    int i = blockIdx.x * blockDim.x + threadIdx.x;
    if (i < N) {
        int o = g_off[i] + g_chunk[i >> 8];
        g_off[i] = o;
        g_cursor[i] = o;
    }
    if (i == 0) g_off[N] = E;
}

// ---------------------------------------------------------------------------
// CSR fill: place each edge into its destination's segment
// ---------------------------------------------------------------------------
__global__ void k_fill(int E, int N) {
    int e = blockIdx.x * blockDim.x + threadIdx.x;
    if (e >= E) return;
    int r = g_row[e];
    int c = g_col[e];
    if ((unsigned)r >= (unsigned)N || (unsigned)c >= (unsigned)N) return;
    int pos = atomicAdd(&g_cursor[c], 1);
    float nrm = g_dinv[r] * g_dinv[c];
    g_edge[pos] = make_int2(r, __float_as_int(nrm));
}

// ---------------------------------------------------------------------------
// GEMM1: g_h[N,128] = x[N,128] @ W1[128,128]
// ---------------------------------------------------------------------------
__global__ void k_gemm1(const float* __restrict__ X, const float* __restrict__ W, int N) {
    __shared__ float Xs[64][33];
    __shared__ float Ws[32][128];

    int t  = threadIdx.x;
    int tx = t & 15;
    int ty = t >> 4;
    int row0 = blockIdx.x * 64;

    float acc[4][8];
#pragma unroll
    for (int i = 0; i < 4; i++)
#pragma unroll
        for (int j = 0; j < 8; j++) acc[i][j] = 0.0f;

    for (int kk = 0; kk < 128; kk += 32) {
        for (int i = t; i < 64 * 32; i += 256) {
            int r = i >> 5, k = i & 31;
            int gr = row0 + r;
            Xs[r][k] = (gr < N) ? X[gr * 128 + kk + k] : 0.0f;
        }
        for (int i = t; i < 32 * 128; i += 256) {
            int k = i >> 7, c = i & 127;
            Ws[k][c] = W[(kk + k) * 128 + c];
        }
        __syncthreads();

#pragma unroll
        for (int k = 0; k < 32; k++) {
            float a[4], b[8];
#pragma unroll
            for (int i = 0; i < 4; i++) a[i] = Xs[ty * 4 + i][k];
#pragma unroll
            for (int j = 0; j < 8; j++) b[j] = Ws[k][tx * 8 + j];
#pragma unroll
            for (int i = 0; i < 4; i++)
#pragma unroll
                for (int j = 0; j < 8; j++) acc[i][j] += a[i] * b[j];
        }
        __syncthreads();
    }

#pragma unroll
    for (int i = 0; i < 4; i++) {
        int gr = row0 + ty * 4 + i;
        if (gr < N) {
            float4* dst = (float4*)&g_h[gr * 128 + tx * 8];
            dst[0] = make_float4(acc[i][0], acc[i][1], acc[i][2], acc[i][3]);
            dst[1] = make_float4(acc[i][4], acc[i][5], acc[i][6], acc[i][7]);
        }
    }
}

// ---------------------------------------------------------------------------
// Gather layer 1 (warp per destination node), fused self-loop + bias + ReLU.
// agg[d] = relu( sum_e nrm_e * h[src_e] + dinv[d]^2 * h[d] + b1 )
// ---------------------------------------------------------------------------
__global__ void __launch_bounds__(256) k_gather1(const float* __restrict__ b1, int N) {
    int w = (blockIdx.x * blockDim.x + threadIdx.x) >> 5;
    int lane = threadIdx.x & 31;
    if (w >= N) return;
    int beg = g_off[w], end = g_off[w + 1];

    float4 acc = make_float4(0.0f, 0.0f, 0.0f, 0.0f);
    int e = beg;
    // 4-way unroll for MLP on the dominant loop
    for (; e + 3 < end; e += 4) {
        int2 p0 = g_edge[e];
        int2 p1 = g_edge[e + 1];
        int2 p2 = g_edge[e + 2];
        int2 p3 = g_edge[e + 3];
        float4 v0 = ((const float4*)g_h)[p0.x * 32 + lane];
        float4 v1 = ((const float4*)g_h)[p1.x * 32 + lane];
        float4 v2 = ((const float4*)g_h)[p2.x * 32 + lane];
        float4 v3 = ((const float4*)g_h)[p3.x * 32 + lane];
        float n0 = __int_as_float(p0.y);
        float n1 = __int_as_float(p1.y);
        float n2 = __int_as_float(p2.y);
        float n3 = __int_as_float(p3.y);
        acc.x += v0.x * n0 + v1.x * n1 + v2.x * n2 + v3.x * n3;
        acc.y += v0.y * n0 + v1.y * n1 + v2.y * n2 + v3.y * n3;
        acc.z += v0.z * n0 + v1.z * n1 + v2.z * n2 + v3.z * n3;
        acc.w += v0.w * n0 + v1.w * n1 + v2.w * n2 + v3.w * n3;
    }
    for (; e < end; e++) {
        int2 p = g_edge[e];
        float n = __int_as_float(p.y);
        float4 v = ((const float4*)g_h)[p.x * 32 + lane];
        acc.x += v.x * n;
        acc.y += v.y * n;
        acc.z += v.z * n;
        acc.w += v.w * n;
    }

    float d = g_dinv[w];
    float di2 = d * d;
    float4 h = ((const float4*)g_h)[w * 32 + lane];
    float4 b = ((const float4*)b1)[lane];
    acc.x = fmaxf(acc.x + di2 * h.x + b.x, 0.0f);
    acc.y = fmaxf(acc.y + di2 * h.y + b.y, 0.0f);
    acc.z = fmaxf(acc.z + di2 * h.z + b.z, 0.0f);
    acc.w = fmaxf(acc.w + di2 * h.w + b.w, 0.0f);
    ((float4*)g_agg)[w * 32 + lane] = acc;
}

// ---------------------------------------------------------------------------
// GEMM2: g_h2[N,16] = g_agg[N,128] @ W2[128,16]
// ---------------------------------------------------------------------------
__global__ void k_gemm2(const float* __restrict__ W2, int N) {
    __shared__ float Ws[128 * 16];
    __shared__ float Xs[64][129];

    int t  = threadIdx.x;
    int tx = t & 15;
    int ty = t >> 4;
    int row0 = blockIdx.x * 64;

    for (int i = t; i < 128 * 16; i += 256) Ws[i] = W2[i];
    for (int i = t; i < 64 * 128; i += 256) {
        int r = i >> 7, k = i & 127;
        int gr = row0 + r;
        Xs[r][k] = (gr < N) ? g_agg[gr * 128 + k] : 0.0f;
    }
    __syncthreads();

    float acc[4] = {0.0f, 0.0f, 0.0f, 0.0f};
#pragma unroll
    for (int k = 0; k < 128; k++) {
        float w = Ws[k * 16 + tx];
#pragma unroll
        for (int i = 0; i < 4; i++) acc[i] += Xs[ty * 4 + i][k] * w;
    }
#pragma unroll
    for (int i = 0; i < 4; i++) {
        int gr = row0 + ty * 4 + i;
        if (gr < N) g_h2[gr * 16 + tx] = acc[i];
    }
}

// ---------------------------------------------------------------------------
// Gather layer 2 fused with self-loop + bias + log_softmax.
// Warp per node; lanes 16-31 mirror lanes 0-15 (broadcast loads, no divergence).
// ---------------------------------------------------------------------------
__global__ void __launch_bounds__(256) k_gather2(const float* __restrict__ b2,
                                                 float* __restrict__ out, int N) {
    int w = (blockIdx.x * blockDim.x + threadIdx.x) >> 5;
    int lane = threadIdx.x & 31;
    int c = lane & 15;
    if (w >= N) return;
    int beg = g_off[w], end = g_off[w + 1];

    float acc = 0.0f;
    int e = beg;
    for (; e + 1 < end; e += 2) {
        int2 p0 = g_edge[e];
        int2 p1 = g_edge[e + 1];
        acc += __int_as_float(p0.y) * g_h2[p0.x * 16 + c]
             + __int_as_float(p1.y) * g_h2[p1.x * 16 + c];
    }
    if (e < end) {
        int2 p = g_edge[e];
        acc += __int_as_float(p.y) * g_h2[p.x * 16 + c];
    }

    float d = g_dinv[w];
    float val = acc + d * d * g_h2[w * 16 + c] + b2[c];

    // max over 16 lanes
    float m = val;
#pragma unroll
    for (int o = 8; o >= 1; o >>= 1)
        m = fmaxf(m, __shfl_xor_sync(0xFFFFFFFFu, m, o, 16));
    // sum of exp
    float s = expf(val - m);
#pragma unroll
    for (int o = 8; o >= 1; o >>= 1)
        s += __shfl_xor_sync(0xFFFFFFFFu, s, o, 16);
    float lse = m + logf(s);

    if (lane < 16) out[w * 16 + c] = val - lse;
}

// ---------------------------------------------------------------------------
extern "C" void kernel_launch(void* const* d_in, const int* in_sizes, int n_in,
                              void* d_out, int out_size) {
    const float* x  = (const float*)d_in[0];
    const void*  ei = (const void*)d_in[1];
    const float* W1 = (const float*)d_in[2];
    const float* b1 = (const float*)d_in[3];
    const float* W2 = (const float*)d_in[4];
    const float* b2 = (const float*)d_in[5];
    float* out = (float*)d_out;

    int N = in_sizes[0] / 128;
    int E = in_sizes[1] / 2;
    int nchunks = (N + 255) / 256;

    // edge conversion + degree
    k_detect<<<1, 32>>>((const unsigned long long*)ei, E);
    k_zero<<<(N + 255) / 256, 256>>>(N);
    k_convert<<<(E + 255) / 256, 256>>>(ei, E, N);
    k_dinv<<<(N + 255) / 256, 256>>>(N);

    // CSR build
    k_scan1<<<nchunks, 256>>>(N);
    k_scan2<<<1, 256>>>(nchunks);
    k_scan3<<<(N + 255) / 256, 256>>>(N, E);
    k_fill<<<(E + 255) / 256, 256>>>(E, N);

    // layer 1
    k_gemm1<<<(N + 63) / 64, 256>>>(x, W1, N);
    k_gather1<<<(N * 32 + 255) / 256, 256>>>(b1, N);

    // layer 2
    k_gemm2<<<(N + 63) / 64, 256>>>(W2, N);
    k_gather2<<<(N * 32 + 255) / 256, 256>>>(b2, out, N);
}

// round 10
// speedup vs baseline: 2.6582x; 1.3407x over previous
#include <cuda_runtime.h>
#include <math.h>
#include <stdint.h>

#define NMAX 50000
#define EMAX 800000

// ===========================================================================
// Scratch (allocation-free rule: __device__ globals)
// ===========================================================================
__device__ float g_h[NMAX * 128];     // x @ W1
__device__ float g_agg[NMAX * 128];   // relu'd hidden after layer-1 aggregation
__device__ float g_h2[NMAX * 16];     // hidden @ W2
__device__ float g_dinv[NMAX];
__device__ int   g_indeg[NMAX];       // in-degree (without self loop)
__device__ int   g_row[EMAX];
__device__ int   g_col[EMAX];
__device__ int   g_off[NMAX + 1];     // CSR offsets by destination
__device__ int   g_chunk[256];        // scan partials
__device__ int   g_cursor[NMAX];      // fill cursors
__device__ int2  g_edge[EMAX];        // CSR payload: (src, __float_as_int(norm))
__device__ int   g_is32;              // 1 if edge_index arrived as int32

// ===========================================================================
// tf32 helpers (plain PTX, supported on base sm_103 target)
// ===========================================================================
__device__ __forceinline__ uint32_t f32_to_tf32(float v) {
    uint32_t r;
    asm("cvt.rna.tf32.f32 %0, %1;" : "=r"(r) : "f"(v));
    return r;
}

__device__ __forceinline__ void mma_tf32(float* d, const uint32_t* a, const uint32_t* b) {
    asm volatile(
        "mma.sync.aligned.m16n8k8.row.col.f32.tf32.tf32.f32 "
        "{%0,%1,%2,%3}, {%4,%5,%6,%7}, {%8,%9}, {%0,%1,%2,%3};"
        : "+f"(d[0]), "+f"(d[1]), "+f"(d[2]), "+f"(d[3])
        : "r"(a[0]), "r"(a[1]), "r"(a[2]), "r"(a[3]), "r"(b[0]), "r"(b[1]));
}

// ===========================================================================
// Edge-prep kernels
// ===========================================================================
__global__ void k_prep(const unsigned long long* __restrict__ ei, int nwords, int N) {
    int i = blockIdx.x * blockDim.x + threadIdx.x;
    if (i < N) g_indeg[i] = 0;
    if (i == 0) {
        int n = nwords < 64 ? nwords : 64;
        unsigned long long acc = 0;
        for (int j = 0; j < n; j++) acc |= (ei[j] >> 32);
        g_is32 = (acc != 0ULL) ? 1 : 0;
    }
}

__global__ void k_convert(const void* __restrict__ ei, int E, int N) {
    int e = blockIdx.x * blockDim.x + threadIdx.x;
    if (e >= E) return;
    int r, c;
    if (g_is32) {
        const int* p = (const int*)ei;
        r = p[e];
        c = p[E + e];
    } else {
        const long long* p = (const long long*)ei;
        r = (int)p[e];
        c = (int)p[E + e];
    }
    g_row[e] = r;
    g_col[e] = c;
    if ((unsigned)c < (unsigned)N) atomicAdd(&g_indeg[c], 1);
}

// scan chunk + dinv fused
__global__ void k_scan1(int N) {
    __shared__ int s[256];
    int t = threadIdx.x;
    int i = blockIdx.x * 256 + t;
    int v = (i < N) ? g_indeg[i] : 0;
    if (i < N) g_dinv[i] = rsqrtf((float)(v + 1));   // +1 self loop
    s[t] = v;
    __syncthreads();
#pragma unroll
    for (int o = 1; o < 256; o <<= 1) {
        int u = (t >= o) ? s[t - o] : 0;
        __syncthreads();
        s[t] += u;
        __syncthreads();
    }
    if (i < N) g_off[i] = s[t] - v;
    if (t == 255) g_chunk[blockIdx.x] = s[255];
}

__global__ void k_scan2(int nchunks) {
    __shared__ int s[256];
    int t = threadIdx.x;
    int v = (t < nchunks) ? g_chunk[t] : 0;
    s[t] = v;
    __syncthreads();
#pragma unroll
    for (int o = 1; o < 256; o <<= 1) {
        int u = (t >= o) ? s[t - o] : 0;
        __syncthreads();
        s[t] += u;
        __syncthreads();
    }
    g_chunk[t] = s[t] - v;
}

__global__ void k_scan3(int N, int E) {
    int i = blockIdx.x * blockDim.x + threadIdx.x;
    if (i < N) {
        int o = g_off[i] + g_chunk[i >> 8];
        g_off[i] = o;
        g_cursor[i] = o;
    }
    if (i == 0) g_off[N] = E;
}

__global__ void k_fill(int E, int N) {
    int e = blockIdx.x * blockDim.x + threadIdx.x;
    if (e >= E) return;
    int r = g_row[e];
    int c = g_col[e];
    if ((unsigned)r >= (unsigned)N || (unsigned)c >= (unsigned)N) return;
    int pos = atomicAdd(&g_cursor[c], 1);
    float nrm = g_dinv[r] * g_dinv[c];
    g_edge[pos] = make_int2(r, __float_as_int(nrm));
}

// ===========================================================================
// GEMM1 via mma.sync tf32 (3xTF32): g_h[N,128] = X[N,128] @ W[128,128]
// CTA tile 128x128, 8 warps in 2(M)x4(N) grid, warp tile 64x32, K chunks of 32.
// SMEM staging with conflict-free padded strides:
//   A [128 x 32] stride 36  -> bank (4r+k)%32 distinct for r%8, k%4
//   B [32 x 128] stride 136 -> bank (8k+c)%32 distinct for k%4, c%8
// ===========================================================================
#define SA_HI 0
#define SA_LO 4608
#define SB_HI 9216
#define SB_LO 13568
#define GM_SMEM_FLOATS 17920
#define GM_SMEM_BYTES (GM_SMEM_FLOATS * 4)

__global__ void __launch_bounds__(256) k_gemm1_mma(const float* __restrict__ X,
                                                   const float* __restrict__ W, int Nn) {
    extern __shared__ float sm[];
    int t = threadIdx.x;
    int lane = t & 31;
    int wid = t >> 5;
    int wm = wid & 1;        // 0..1: M band (64 rows)
    int wn = wid >> 1;       // 0..3: N band (32 cols)
    int row0 = blockIdx.x * 128;

    float acc[4][4][4];
#pragma unroll
    for (int mt = 0; mt < 4; mt++)
#pragma unroll
        for (int nt = 0; nt < 4; nt++)
#pragma unroll
            for (int q = 0; q < 4; q++) acc[mt][nt][q] = 0.0f;

    int lq = lane >> 2;      // 0..7
    int lr = lane & 3;       // 0..3

    for (int kk = 0; kk < 128; kk += 32) {
        // ---- stage A (128 rows x 32 k) hi/lo ----
        for (int i = t; i < 4096; i += 256) {
            int r = i >> 5, k = i & 31;
            int gr = row0 + r;
            float v = (gr < Nn) ? X[gr * 128 + kk + k] : 0.0f;
            float hf = __uint_as_float(f32_to_tf32(v));
            float lf = __uint_as_float(f32_to_tf32(v - hf));
            sm[SA_HI + r * 36 + k] = hf;
            sm[SA_LO + r * 36 + k] = lf;
        }
        // ---- stage B (32 k x 128 n) hi/lo ----
        for (int i = t; i < 4096; i += 256) {
            int n = i & 127, k = i >> 7;
            float v = W[(kk + k) * 128 + n];
            float hf = __uint_as_float(f32_to_tf32(v));
            float lf = __uint_as_float(f32_to_tf32(v - hf));
            sm[SB_HI + k * 136 + n] = hf;
            sm[SB_LO + k * 136 + n] = lf;
        }
        __syncthreads();

#pragma unroll
        for (int ks = 0; ks < 4; ks++) {
            int kb = ks * 8;
            uint32_t af[4][4], bh[4][2], bl[4][2];
            // A_hi fragments
#pragma unroll
            for (int mt = 0; mt < 4; mt++) {
                int ra = wm * 64 + mt * 16 + lq;
                int ka = kb + lr;
                af[mt][0] = __float_as_uint(sm[SA_HI + ra * 36 + ka]);
                af[mt][1] = __float_as_uint(sm[SA_HI + (ra + 8) * 36 + ka]);
                af[mt][2] = __float_as_uint(sm[SA_HI + ra * 36 + ka + 4]);
                af[mt][3] = __float_as_uint(sm[SA_HI + (ra + 8) * 36 + ka + 4]);
            }
            // B_hi / B_lo fragments
#pragma unroll
            for (int nt = 0; nt < 4; nt++) {
                int cb = wn * 32 + nt * 8 + lq;
                int kbb = kb + lr;
                bh[nt][0] = __float_as_uint(sm[SB_HI + kbb * 136 + cb]);
                bh[nt][1] = __float_as_uint(sm[SB_HI + (kbb + 4) * 136 + cb]);
                bl[nt][0] = __float_as_uint(sm[SB_LO + kbb * 136 + cb]);
                bl[nt][1] = __float_as_uint(sm[SB_LO + (kbb + 4) * 136 + cb]);
            }
            // hi*hi and hi*lo
#pragma unroll
            for (int mt = 0; mt < 4; mt++)
#pragma unroll
                for (int nt = 0; nt < 4; nt++) {
                    mma_tf32(acc[mt][nt], af[mt], bh[nt]);
                    mma_tf32(acc[mt][nt], af[mt], bl[nt]);
                }
            // reload A_lo into af, then lo*hi
#pragma unroll
            for (int mt = 0; mt < 4; mt++) {
                int ra = wm * 64 + mt * 16 + lq;
                int ka = kb + lr;
                af[mt][0] = __float_as_uint(sm[SA_LO + ra * 36 + ka]);
                af[mt][1] = __float_as_uint(sm[SA_LO + (ra + 8) * 36 + ka]);
                af[mt][2] = __float_as_uint(sm[SA_LO + ra * 36 + ka + 4]);
                af[mt][3] = __float_as_uint(sm[SA_LO + (ra + 8) * 36 + ka + 4]);
            }
#pragma unroll
            for (int mt = 0; mt < 4; mt++)
#pragma unroll
                for (int nt = 0; nt < 4; nt++)
                    mma_tf32(acc[mt][nt], af[mt], bh[nt]);
        }
        __syncthreads();
    }

    // ---- epilogue: write acc to g_h ----
#pragma unroll
    for (int mt = 0; mt < 4; mt++) {
        int r0 = row0 + wm * 64 + mt * 16 + lq;
#pragma unroll
        for (int nt = 0; nt < 4; nt++) {
            int c0 = wn * 32 + nt * 8 + 2 * lr;
            if (r0 < Nn)
                *(float2*)&g_h[r0 * 128 + c0] = make_float2(acc[mt][nt][0], acc[mt][nt][1]);
            if (r0 + 8 < Nn)
                *(float2*)&g_h[(r0 + 8) * 128 + c0] = make_float2(acc[mt][nt][2], acc[mt][nt][3]);
        }
    }
}

// ===========================================================================
// Gather layer 1 (warp per destination node), fused self-loop + bias + ReLU.
// ===========================================================================
__global__ void __launch_bounds__(256) k_gather1(const float* __restrict__ b1, int N) {
    int w = (blockIdx.x * blockDim.x + threadIdx.x) >> 5;
    int lane = threadIdx.x & 31;
    if (w >= N) return;
    int beg = g_off[w], end = g_off[w + 1];

    float4 acc = make_float4(0.0f, 0.0f, 0.0f, 0.0f);
    int e = beg;
    for (; e + 3 < end; e += 4) {
        int2 p0 = g_edge[e];
        int2 p1 = g_edge[e + 1];
        int2 p2 = g_edge[e + 2];
        int2 p3 = g_edge[e + 3];
        float4 v0 = ((const float4*)g_h)[p0.x * 32 + lane];
        float4 v1 = ((const float4*)g_h)[p1.x * 32 + lane];
        float4 v2 = ((const float4*)g_h)[p2.x * 32 + lane];
        float4 v3 = ((const float4*)g_h)[p3.x * 32 + lane];
        float n0 = __int_as_float(p0.y);
        float n1 = __int_as_float(p1.y);
        float n2 = __int_as_float(p2.y);
        float n3 = __int_as_float(p3.y);
        acc.x += v0.x * n0 + v1.x * n1 + v2.x * n2 + v3.x * n3;
        acc.y += v0.y * n0 + v1.y * n1 + v2.y * n2 + v3.y * n3;
        acc.z += v0.z * n0 + v1.z * n1 + v2.z * n2 + v3.z * n3;
        acc.w += v0.w * n0 + v1.w * n1 + v2.w * n2 + v3.w * n3;
    }
    for (; e < end; e++) {
        int2 p = g_edge[e];
        float n = __int_as_float(p.y);
        float4 v = ((const float4*)g_h)[p.x * 32 + lane];
        acc.x += v.x * n;
        acc.y += v.y * n;
        acc.z += v.z * n;
        acc.w += v.w * n;
    }

    float d = g_dinv[w];
    float di2 = d * d;
    float4 h = ((const float4*)g_h)[w * 32 + lane];
    float4 b = ((const float4*)b1)[lane];
    acc.x = fmaxf(acc.x + di2 * h.x + b.x, 0.0f);
    acc.y = fmaxf(acc.y + di2 * h.y + b.y, 0.0f);
    acc.z = fmaxf(acc.z + di2 * h.z + b.z, 0.0f);
    acc.w = fmaxf(acc.w + di2 * h.w + b.w, 0.0f);
    ((float4*)g_agg)[w * 32 + lane] = acc;
}

// ===========================================================================
// GEMM2: g_h2[N,16] = g_agg[N,128] @ W2[128,16]  (SIMT; small)
// ===========================================================================
__global__ void k_gemm2(const float* __restrict__ W2, int N) {
    __shared__ float Ws[128 * 16];
    __shared__ float Xs[64][129];

    int t  = threadIdx.x;
    int tx = t & 15;
    int ty = t >> 4;
    int row0 = blockIdx.x * 64;

    for (int i = t; i < 128 * 16; i += 256) Ws[i] = W2[i];
    for (int i = t; i < 64 * 128; i += 256) {
        int r = i >> 7, k = i & 127;
        int gr = row0 + r;
        Xs[r][k] = (gr < N) ? g_agg[gr * 128 + k] : 0.0f;
    }
    __syncthreads();

    float acc[4] = {0.0f, 0.0f, 0.0f, 0.0f};
#pragma unroll
    for (int k = 0; k < 128; k++) {
        float w = Ws[k * 16 + tx];
#pragma unroll
        for (int i = 0; i < 4; i++) acc[i] += Xs[ty * 4 + i][k] * w;
    }
#pragma unroll
    for (int i = 0; i < 4; i++) {
        int gr = row0 + ty * 4 + i;
        if (gr < N) g_h2[gr * 16 + tx] = acc[i];
    }
}

// ===========================================================================
// Gather layer 2 fused with self-loop + bias + log_softmax.
// ===========================================================================
__global__ void __launch_bounds__(256) k_gather2(const float* __restrict__ b2,
                                                 float* __restrict__ out, int N) {
    int w = (blockIdx.x * blockDim.x + threadIdx.x) >> 5;
    int lane = threadIdx.x & 31;
    int c = lane & 15;
    if (w >= N) return;
    int beg = g_off[w], end = g_off[w + 1];

    float acc = 0.0f;
    int e = beg;
    for (; e + 1 < end; e += 2) {
        int2 p0 = g_edge[e];
        int2 p1 = g_edge[e + 1];
        acc += __int_as_float(p0.y) * g_h2[p0.x * 16 + c]
             + __int_as_float(p1.y) * g_h2[p1.x * 16 + c];
    }
    if (e < end) {
        int2 p = g_edge[e];
        acc += __int_as_float(p.y) * g_h2[p.x * 16 + c];
    }

    float d = g_dinv[w];
    float val = acc + d * d * g_h2[w * 16 + c] + b2[c];

    float m = val;
#pragma unroll
    for (int o = 8; o >= 1; o >>= 1)
        m = fmaxf(m, __shfl_xor_sync(0xFFFFFFFFu, m, o, 16));
    float s = expf(val - m);
#pragma unroll
    for (int o = 8; o >= 1; o >>= 1)
        s += __shfl_xor_sync(0xFFFFFFFFu, s, o, 16);
    float lse = m + logf(s);

    if (lane < 16) out[w * 16 + c] = val - lse;
}

// ===========================================================================
extern "C" void kernel_launch(void* const* d_in, const int* in_sizes, int n_in,
                              void* d_out, int out_size) {
    const float* x  = (const float*)d_in[0];
    const void*  ei = (const void*)d_in[1];
    const float* W1 = (const float*)d_in[2];
    const float* b1 = (const float*)d_in[3];
    const float* W2 = (const float*)d_in[4];
    const float* b2 = (const float*)d_in[5];
    float* out = (float*)d_out;

    int N = in_sizes[0] / 128;
    int E = in_sizes[1] / 2;
    int nchunks = (N + 255) / 256;

    static cudaStream_t s2 = nullptr;
    static cudaEvent_t evFork = nullptr, evJoin = nullptr;
    static int inited = 0;
    if (!inited) {
        cudaFuncSetAttribute(k_gemm1_mma, cudaFuncAttributeMaxDynamicSharedMemorySize,
                             GM_SMEM_BYTES);
        cudaStreamCreateWithFlags(&s2, cudaStreamNonBlocking);
        cudaEventCreateWithFlags(&evFork, cudaEventDisableTiming);
        cudaEventCreateWithFlags(&evJoin, cudaEventDisableTiming);
        inited = 1;
    }

    // Fork: CSR build chain on s2, GEMM1 on main stream (independent work).
    cudaEventRecord(evFork, 0);
    cudaStreamWaitEvent(s2, evFork, 0);

    k_prep<<<(N + 255) / 256, 256, 0, s2>>>((const unsigned long long*)ei, E, N);
    k_convert<<<(E + 255) / 256, 256, 0, s2>>>(ei, E, N);
    k_scan1<<<nchunks, 256, 0, s2>>>(N);
    k_scan2<<<1, 256, 0, s2>>>(nchunks);
    k_scan3<<<(N + 255) / 256, 256, 0, s2>>>(N, E);
    k_fill<<<(E + 255) / 256, 256, 0, s2>>>(E, N);
    cudaEventRecord(evJoin, s2);

    // layer 1 GEMM (tensor pipe) runs concurrently with CSR build
    k_gemm1_mma<<<(N + 127) / 128, 256, GM_SMEM_BYTES>>>(x, W1, N);

    // Join: gather needs both CSR and GEMM1
    cudaStreamWaitEvent(0, evJoin, 0);

    k_gather1<<<(N * 32 + 255) / 256, 256>>>(b1, N);
    k_gemm2<<<(N + 63) / 64, 256>>>(W2, N);
    k_gather2<<<(N * 32 + 255) / 256, 256>>>(b2, out, N);
}